// round 16
// baseline (speedup 1.0000x reference)
#include <cuda_runtime.h>
#include <cuda_fp16.h>
#include <cstdint>

#define NN 20000
#define EE 320000
#define DD 1280
#define GG 64
#define FPD 65

// ======================= scratch =======================
__device__ __half g_xh[(size_t)NN * DD];   // fp16 copy of input x
__device__ __half g_h[(size_t)NN * DD];    // GEMM output (fp16)
__device__ __half g_act[(size_t)NN * DD];  // aggregated + activated (fp16)
__device__ __half g_wt[(size_t)DD * DD];   // transposed fp16 weights [Nout][K]
__device__ float g_dis[NN];
__device__ int   g_ecnt[NN];
__device__ int   g_off[NN + 1];
__device__ int   g_cur[NN];
__device__ int   g_csrc[EE];
__device__ float g_cw[EE];
__device__ int   g_gcnt[GG];
__device__ int   g_goff[GG + 1];
__device__ float g_pool[GG * 320];
__device__ float g_t1[GG * 1024];
__device__ float g_t2[GG * 128];
__device__ float g_cat[GG * 193];
__device__ float g_t3[GG * 512];

// ======================= helpers =======================
__device__ __forceinline__ uint32_t smem_u32(const void* p) {
    uint32_t a;
    asm("{ .reg .u64 tmp; cvta.to.shared.u64 tmp, %1; cvt.u32.u64 %0, tmp; }"
        : "=r"(a) : "l"(p));
    return a;
}

__device__ __forceinline__ void cp_async16(uint32_t saddr, const void* gptr, int src_bytes) {
    asm volatile("cp.async.cg.shared.global [%0], [%1], 16, %2;"
                 :: "r"(saddr), "l"(gptr), "r"(src_bytes));
}
#define CP_COMMIT() asm volatile("cp.async.commit_group;" ::: "memory")
#define CP_WAIT1()  asm volatile("cp.async.wait_group 1;" ::: "memory")

// m16n8k16 fp16 mma, fp32 accumulate
__device__ __forceinline__ void mma_f16(float* c, const uint32_t* a, const uint32_t* b) {
    asm volatile(
        "mma.sync.aligned.m16n8k16.row.col.f32.f16.f16.f32 "
        "{%0,%1,%2,%3}, {%4,%5,%6,%7}, {%8,%9}, {%0,%1,%2,%3};"
        : "+f"(c[0]), "+f"(c[1]), "+f"(c[2]), "+f"(c[3])
        : "r"(a[0]), "r"(a[1]), "r"(a[2]), "r"(a[3]), "r"(b[0]), "r"(b[1]));
}

// ======================= CSR build =======================
__global__ void k_count(const int* __restrict__ dst) {
    int i = blockIdx.x * blockDim.x + threadIdx.x;
    if (i < EE) atomicAdd(&g_ecnt[dst[i]], 1);
}

__global__ void k_dis() {
    int i = blockIdx.x * blockDim.x + threadIdx.x;
    if (i < NN) g_dis[i] = rsqrtf((float)(g_ecnt[i] + 1));
}

__global__ __launch_bounds__(1024) void k_scan() {
    __shared__ int s[1024];
    __shared__ int carry_s;
    int t = threadIdx.x;
    if (t == 0) carry_s = 0;
    __syncthreads();
    for (int base = 0; base < NN; base += 1024) {
        int v = (base + t < NN) ? g_ecnt[base + t] : 0;
        s[t] = v;
        __syncthreads();
        for (int off = 1; off < 1024; off <<= 1) {
            int x = (t >= off) ? s[t - off] : 0;
            __syncthreads();
            s[t] += x;
            __syncthreads();
        }
        int carry = carry_s;
        if (base + t < NN) g_off[base + t] = carry + s[t] - v;
        __syncthreads();
        if (t == 0) carry_s = carry + s[1023];
        __syncthreads();
    }
    if (t == 0) g_off[NN] = carry_s;
}

__global__ void k_bucket(const int* __restrict__ src, const int* __restrict__ dst) {
    int e = blockIdx.x * blockDim.x + threadIdx.x;
    if (e < EE) {
        int d = dst[e];
        int s = src[e];
        int p = atomicAdd(&g_cur[d], 1);
        g_csrc[p] = s;
        g_cw[p] = g_dis[s] * g_dis[d];
    }
}

__global__ void k_gcnt(const int* __restrict__ batch) {
    int i = blockIdx.x * blockDim.x + threadIdx.x;
    if (i < NN) atomicAdd(&g_gcnt[batch[i]], 1);
}

__global__ void k_gscan() {
    if (threadIdx.x == 0) {
        int acc = 0;
        for (int g = 0; g < GG; g++) { g_goff[g] = acc; acc += g_gcnt[g]; }
        g_goff[GG] = acc;
    }
}

// ======================= x -> fp16 =======================
__global__ void k_tohalf(const float* __restrict__ in, __half* __restrict__ out, int n) {
    int i = blockIdx.x * blockDim.x + threadIdx.x;
    if (i * 2 + 1 < n) {
        float2 v = *(const float2*)&in[i * 2];
        *(__half2*)&out[i * 2] = __floats2half2_rn(v.x, v.y);
    }
}

// ======================= weight transpose + fp16: Wt[n][k] = W[k][n] =======================
__global__ __launch_bounds__(256) void k_transpose_h(const float* __restrict__ W,
                                                     __half* __restrict__ Wt,
                                                     int K, int Nout) {
    __shared__ float tile[32][33];
    int kb = blockIdx.y * 32, nb = blockIdx.x * 32;
    int tx = threadIdx.x & 31, ty = threadIdx.x >> 5;  // 32x8
#pragma unroll
    for (int i = 0; i < 32; i += 8) {
        int kk = kb + ty + i, n = nb + tx;
        if (kk < K && n < Nout) tile[ty + i][tx] = W[(size_t)kk * Nout + n];
    }
    __syncthreads();
#pragma unroll
    for (int i = 0; i < 32; i += 8) {
        int n = nb + ty + i, kk = kb + tx;
        if (n < Nout && kk < K) Wt[(size_t)n * K + kk] = __float2half_rn(tile[tx][ty + i]);
    }
}

// ======================= fp16 mma.sync GEMM, cp.async double-buffered =======================
// C(fp16)[M,Nout] = A(fp16)[M,K] @ Wt(fp16)[Nout,K]^T.  BM=128, BN template, BK=32.
// 8 warps: warp_m = wid&3 (32 rows), warp_n = wid>>2 (BN/2 cols).
// Row stride 40 halves (80B): conflict-free half2 fragment reads, 16B-aligned cp.async.
template <int BN>
__global__ __launch_bounds__(256) void k_gemm_mma(
    const __half* __restrict__ A, const __half* __restrict__ Bt,
    __half* __restrict__ C, int M, int K, int Nout) {
    constexpr int NT = BN / 16;  // n8-tiles per warp
    __shared__ __half sA[2][128][40];
    __shared__ __half sB[2][BN][40];

    int t = threadIdx.x;
    int wid = t >> 5, lane = t & 31;
    int grp = lane >> 2, tig = lane & 3;
    int warp_m = wid & 3, warp_n = wid >> 2;
    int m0 = blockIdx.y * 128, n0 = blockIdx.x * BN;

    uint32_t aA = smem_u32(sA);
    uint32_t aB = smem_u32(sB);

    float acc[2][NT][4];
#pragma unroll
    for (int mt = 0; mt < 2; mt++)
#pragma unroll
        for (int nt = 0; nt < NT; nt++)
#pragma unroll
            for (int i = 0; i < 4; i++) acc[mt][nt][i] = 0.0f;

    int nk = K >> 5;

    auto load_tiles = [&](int buf, int k0) {
        // A tile: 128 rows x 32 halves = 64B/row = 4 x 16B chunks; 512 chunks, 2/thread
#pragma unroll
        for (int i = 0; i < 2; i++) {
            int v = t + i * 256;
            int row = v >> 2, c8 = (v & 3) * 8;  // halves
            int grow = m0 + row;
            const __half* src = &A[(size_t)((grow < M) ? grow : 0) * K + k0 + c8];
            int sz = (grow < M) ? 16 : 0;
            cp_async16(aA + (uint32_t)(((buf * 128 + row) * 40 + c8) * 2), src, sz);
        }
        // B tile: BN rows x 32 halves = BN*4 chunks
#pragma unroll
        for (int i = 0; i < BN / 64; i++) {
            int v = t + i * 256;
            int row = v >> 2, c8 = (v & 3) * 8;
            const __half* src = &Bt[(size_t)(n0 + row) * K + k0 + c8];
            cp_async16(aB + (uint32_t)(((buf * BN + row) * 40 + c8) * 2), src, 16);
        }
    };

    load_tiles(0, 0);
    CP_COMMIT();

    for (int kt = 0; kt < nk; kt++) {
        int buf = kt & 1;
        if (kt + 1 < nk) load_tiles(buf ^ 1, (kt + 1) << 5);
        CP_COMMIT();
        CP_WAIT1();
        __syncthreads();

#pragma unroll
        for (int ks = 0; ks < 2; ks++) {
            int kk = ks * 16;
            uint32_t af[2][4];
#pragma unroll
            for (int mt = 0; mt < 2; mt++) {
                int r = warp_m * 32 + mt * 16;
                af[mt][0] = *(const uint32_t*)&sA[buf][r + grp][kk + 2 * tig];
                af[mt][1] = *(const uint32_t*)&sA[buf][r + grp + 8][kk + 2 * tig];
                af[mt][2] = *(const uint32_t*)&sA[buf][r + grp][kk + 2 * tig + 8];
                af[mt][3] = *(const uint32_t*)&sA[buf][r + grp + 8][kk + 2 * tig + 8];
            }
#pragma unroll
            for (int nt = 0; nt < NT; nt++) {
                int c = warp_n * (NT * 8) + nt * 8;
                uint32_t bf[2];
                bf[0] = *(const uint32_t*)&sB[buf][c + grp][kk + 2 * tig];
                bf[1] = *(const uint32_t*)&sB[buf][c + grp][kk + 2 * tig + 8];
                mma_f16(acc[0][nt], af[0], bf);
                mma_f16(acc[1][nt], af[1], bf);
            }
        }
        __syncthreads();
    }

    // epilogue: fp32 acc -> fp16 store
#pragma unroll
    for (int mt = 0; mt < 2; mt++) {
        int r0 = m0 + warp_m * 32 + mt * 16 + grp;
#pragma unroll
        for (int nt = 0; nt < NT; nt++) {
            int col = n0 + warp_n * (NT * 8) + nt * 8 + tig * 2;
            if (r0 < M) {
                __half2 v = __floats2half2_rn(acc[mt][nt][0], acc[mt][nt][1]);
                *(__half2*)&C[(size_t)r0 * Nout + col] = v;
            }
            if (r0 + 8 < M) {
                __half2 v = __floats2half2_rn(acc[mt][nt][2], acc[mt][nt][3]);
                *(__half2*)&C[(size_t)(r0 + 8) * Nout + col] = v;
            }
        }
    }
}

// ======================= CSR gather + bias + relu (fp16 in/out, fp32 accum) =======================
__global__ void k_gather(const __half* __restrict__ h, const float* __restrict__ bias,
                         __half* __restrict__ out, int Dout) {
    int d = blockIdx.x;
    int f4 = threadIdx.x;

    float wd = g_dis[d];
    float selfw = wd * wd;

    auto load4 = [&](int node) -> float4 {
        uint2 u = ((const uint2*)(h + (size_t)node * Dout))[f4];
        float2 p0 = __half22float2(*(__half2*)&u.x);
        float2 p1 = __half22float2(*(__half2*)&u.y);
        return make_float4(p0.x, p0.y, p1.x, p1.y);
    };

    float4 hv = load4(d);
    float4 acc = make_float4(hv.x * selfw, hv.y * selfw, hv.z * selfw, hv.w * selfw);

    int j = g_off[d];
    int jend = g_off[d + 1];
    for (; j + 1 < jend; j += 2) {
        int sa = g_csrc[j], sb = g_csrc[j + 1];
        float wa = g_cw[j], wb = g_cw[j + 1];
        float4 ha = load4(sa);
        float4 hb = load4(sb);
        acc.x += ha.x * wa + hb.x * wb;
        acc.y += ha.y * wa + hb.y * wb;
        acc.z += ha.z * wa + hb.z * wb;
        acc.w += ha.w * wa + hb.w * wb;
    }
    if (j < jend) {
        int sa = g_csrc[j];
        float wa = g_cw[j];
        float4 ha = load4(sa);
        acc.x += ha.x * wa;
        acc.y += ha.y * wa;
        acc.z += ha.z * wa;
        acc.w += ha.w * wa;
    }

    float4 bv = ((const float4*)bias)[f4];
    acc.x = fmaxf(acc.x + bv.x, 0.0f);
    acc.y = fmaxf(acc.y + bv.y, 0.0f);
    acc.z = fmaxf(acc.z + bv.z, 0.0f);
    acc.w = fmaxf(acc.w + bv.w, 0.0f);
    uint2 o;
    *(__half2*)&o.x = __floats2half2_rn(acc.x, acc.y);
    *(__half2*)&o.y = __floats2half2_rn(acc.z, acc.w);
    ((uint2*)(out + (size_t)d * Dout))[f4] = o;
}

// ======================= pool (fp16 src, fp32 out) + head =======================
__global__ __launch_bounds__(320) void k_pool(const __half* __restrict__ act) {
    int g = blockIdx.x;
    int f = threadIdx.x;
    int n0 = g_goff[g], n1 = g_goff[g + 1];
    float acc = 0.0f;
    for (int n = n0; n < n1; n++) acc += __half2float(act[(size_t)n * 320 + f]);
    float c = (float)(n1 - n0);
    g_pool[g * 320 + f] = acc / fmaxf(c, 1.0f);
}

__global__ __launch_bounds__(256) void k_dense(
    const float* __restrict__ A, const float* __restrict__ W,
    const float* __restrict__ b, float* __restrict__ C,
    int K, int Nout, int relu) {
    __shared__ float row[1024];
    int g = blockIdx.x;
    for (int k = threadIdx.x; k < K; k += blockDim.x) row[k] = A[g * K + k];
    __syncthreads();
    for (int n = threadIdx.x; n < Nout; n += blockDim.x) {
        float s = b[n];
        for (int k = 0; k < K; k++) s += row[k] * W[(size_t)k * Nout + n];
        if (relu) s = fmaxf(s, 0.0f);
        C[g * Nout + n] = s;
    }
}

__global__ void k_concat(const float* __restrict__ fp) {
    int idx = blockIdx.x * blockDim.x + threadIdx.x;
    if (idx < GG * 193) {
        int g = idx / 193;
        int f = idx - g * 193;
        g_cat[idx] = (f < FPD) ? fp[g * FPD + f] : g_t2[g * 128 + (f - FPD)];
    }
}

// ======================= host driver =======================
static void run_layer(const __half* X, const float* W, const float* bias,
                      int K, int Dout, __half* hbuf, __half* actbuf, __half* wtp) {
    dim3 tgrid(Dout / 32, K / 32);
    k_transpose_h<<<tgrid, 256>>>(W, wtp, K, Dout);
    if (Dout % 128 == 0) {
        dim3 grid(Dout / 128, (NN + 127) / 128);
        k_gemm_mma<128><<<grid, 256>>>(X, wtp, hbuf, NN, K, Dout);
    } else {
        dim3 grid(Dout / 64, (NN + 127) / 128);
        k_gemm_mma<64><<<grid, 256>>>(X, wtp, hbuf, NN, K, Dout);
    }
    k_gather<<<NN, Dout / 4>>>(hbuf, bias, actbuf, Dout);
}

extern "C" void kernel_launch(void* const* d_in, const int* in_sizes, int n_in,
                              void* d_out, int out_size) {
    const float* x     = (const float*)d_in[0];
    const int*   ei    = (const int*)d_in[1];
    const int*   batch = (const int*)d_in[2];
    const float* fp    = (const float*)d_in[3];
    const float* W1 = (const float*)d_in[4];
    const float* b1 = (const float*)d_in[5];
    const float* W2 = (const float*)d_in[6];
    const float* b2 = (const float*)d_in[7];
    const float* W3 = (const float*)d_in[8];
    const float* b3 = (const float*)d_in[9];
    const float* Wg1 = (const float*)d_in[10];
    const float* bg1 = (const float*)d_in[11];
    const float* Wg2 = (const float*)d_in[12];
    const float* bg2 = (const float*)d_in[13];
    const float* Wf1 = (const float*)d_in[14];
    const float* bf1 = (const float*)d_in[15];
    const float* Wf2 = (const float*)d_in[16];
    const float* bf2 = (const float*)d_in[17];
    const float* Wo  = (const float*)d_in[18];
    const float* bo  = (const float*)d_in[19];
    float* out = (float*)d_out;

    const int* src = ei;
    const int* dst = ei + EE;

    float *poolp, *t1p, *t2p, *catp, *t3p;
    __half *xhp, *hbuf, *actbuf, *wtp;
    int *ecntp, *offp, *curp, *gcntp;
    cudaGetSymbolAddress((void**)&xhp, g_xh);
    cudaGetSymbolAddress((void**)&hbuf, g_h);
    cudaGetSymbolAddress((void**)&actbuf, g_act);
    cudaGetSymbolAddress((void**)&wtp, g_wt);
    cudaGetSymbolAddress((void**)&poolp, g_pool);
    cudaGetSymbolAddress((void**)&t1p, g_t1);
    cudaGetSymbolAddress((void**)&t2p, g_t2);
    cudaGetSymbolAddress((void**)&catp, g_cat);
    cudaGetSymbolAddress((void**)&t3p, g_t3);
    cudaGetSymbolAddress((void**)&ecntp, g_ecnt);
    cudaGetSymbolAddress((void**)&offp, g_off);
    cudaGetSymbolAddress((void**)&curp, g_cur);
    cudaGetSymbolAddress((void**)&gcntp, g_gcnt);

    // ---- CSR + norm build ----
    cudaMemsetAsync(ecntp, 0, NN * sizeof(int), 0);
    cudaMemsetAsync(gcntp, 0, GG * sizeof(int), 0);
    k_count<<<(EE + 255) / 256, 256>>>(dst);
    k_dis<<<(NN + 255) / 256, 256>>>();
    k_scan<<<1, 1024>>>();
    cudaMemcpyAsync(curp, offp, NN * sizeof(int), cudaMemcpyDeviceToDevice, 0);
    k_bucket<<<(EE + 255) / 256, 256>>>(src, dst);
    k_gcnt<<<(NN + 255) / 256, 256>>>(batch);
    k_gscan<<<1, 32>>>();

    // ---- x -> fp16 ----
    k_tohalf<<<(NN * DD / 2 + 255) / 256, 256>>>(x, xhp, NN * DD);

    // ---- three GCN layers (fp16 mma.sync GEMMs) ----
    run_layer(xhp,    W1, b1, DD,  DD,  hbuf, actbuf, wtp);
    run_layer(actbuf, W2, b2, DD,  640, hbuf, actbuf, wtp);
    run_layer(actbuf, W3, b3, 640, 320, hbuf, actbuf, wtp);

    // ---- global mean pool ----
    k_pool<<<GG, 320>>>(actbuf);

    // ---- MLP head ----
    k_dense<<<GG, 256>>>(poolp, Wg1, bg1, t1p, 320, 1024, 1);
    k_dense<<<GG, 256>>>(t1p, Wg2, bg2, t2p, 1024, 128, 0);
    k_concat<<<(GG * 193 + 255) / 256, 256>>>(fp);
    k_dense<<<GG, 256>>>(catp, Wf1, bf1, t1p, 193, 1024, 1);
    k_dense<<<GG, 256>>>(t1p, Wf2, bf2, t3p, 1024, 512, 1);
    k_dense<<<GG, 256>>>(t3p, Wo, bo, out, 512, 1, 0);

    (void)in_sizes; (void)n_in; (void)out_size;
}